// round 15
// baseline (speedup 1.0000x reference)
#include <cuda_runtime.h>
#include <cuda_fp16.h>

#define NN 100000
#define EE 1200000
#define NB 98            // ceil(NN / 1024)

// ---------------- scratch (device globals; no allocation allowed) ------------
__device__ __align__(16) int    g_degi[NN];
__device__ __align__(16) int    g_cnt [NN];
__device__ __align__(16) int    g_ptr [NN];       // CSR row start (exclusive scan)
__device__ __align__(16) int    g_bsum[NB];
__device__ __align__(16) float  g_dis [NN];
__device__ __align__(16) int2   g_csr_cw[EE];     // packed {col, w-as-bits}
// fp16 intermediates
__device__ __align__(16) __half g_H16  [(size_t)NN * 64];
__device__ __align__(16) __half g_B16  [(size_t)NN * 64];
__device__ __align__(16) __half g_C216 [(size_t)NN * 64];
__device__ __align__(16) __half g_B216 [(size_t)NN * 32];
__device__ __align__(16) __half g_C2216[(size_t)NN * 32];
// pre-transposed fp16 weights in EXACT smem layout ([q][n][k], row stride 72)
__device__ __align__(16) __half g_W1t[3 * 64 * 72];
__device__ __align__(16) __half g_W2t[3 * 32 * 72];

// ---------------- helpers ------------------------------------------------------
__device__ __forceinline__ float2 h2f(unsigned u) {
    __half2 h = *reinterpret_cast<__half2*>(&u);
    return __half22float2(h);
}
__device__ __forceinline__ unsigned f2h(float a, float b) {
    __half2 h = __floats2half2_rn(a, b);
    return *reinterpret_cast<unsigned*>(&h);
}
__device__ __forceinline__ unsigned hrelu(unsigned u) {
    __half2 h = *reinterpret_cast<__half2*>(&u);
    h = __hmax2(h, __floats2half2_rn(0.f, 0.f));
    return *reinterpret_cast<unsigned*>(&h);
}
__device__ __forceinline__ unsigned sptr(const void* p) {
    return (unsigned)__cvta_generic_to_shared(p);
}
__device__ __forceinline__ void ldsm_x4(unsigned& r0, unsigned& r1, unsigned& r2,
                                        unsigned& r3, unsigned addr) {
    asm volatile("ldmatrix.sync.aligned.m8n8.x4.shared.b16 {%0,%1,%2,%3}, [%4];"
                 : "=r"(r0), "=r"(r1), "=r"(r2), "=r"(r3) : "r"(addr));
}
__device__ __forceinline__ void mma_16816(float* c, unsigned a0, unsigned a1,
                                          unsigned a2, unsigned a3,
                                          unsigned b0, unsigned b1) {
    asm volatile(
        "mma.sync.aligned.m16n8k16.row.col.f32.f16.f16.f32 "
        "{%0,%1,%2,%3}, {%4,%5,%6,%7}, {%8,%9}, {%0,%1,%2,%3};"
        : "+f"(c[0]), "+f"(c[1]), "+f"(c[2]), "+f"(c[3])
        : "r"(a0), "r"(a1), "r"(a2), "r"(a3), "r"(b0), "r"(b1));
}

// ---------------- one-time weight prep (fold, transpose, fp16) ----------------
__global__ __launch_bounds__(384) void k_wprep(const float* __restrict__ W1,
                                               const float* __restrict__ W2) {
    int tid = blockIdx.x * 384 + threadIdx.x;
    int stride = gridDim.x * 384;
    for (int i = tid; i < 3 * 64 * 64; i += stride) {
        int q = i >> 12, rem = i & 4095;
        int n = rem >> 6, k = rem & 63;
        float w = W1[q * 4096 + k * 64 + n];
        if (q == 0) w -= W1[2 * 4096 + k * 64 + n];
        g_W1t[q * 64 * 72 + n * 72 + k] = __float2half_rn(w);
    }
    for (int i = tid; i < 3 * 32 * 64; i += stride) {
        int q = i >> 11, rem = i & 2047;
        int n = rem >> 6, k = rem & 63;
        float w = W2[q * 2048 + k * 32 + n];
        if (q == 0) w -= W2[2 * 2048 + k * 32 + n];
        g_W2t[q * 32 * 72 + n * 72 + k] = __float2half_rn(w);
    }
}

// ---------------- degree / CSR build -----------------------------------------
__global__ void k_init() {
    int i = blockIdx.x * blockDim.x + threadIdx.x;
    if (i < NN) { g_degi[i] = 0; g_cnt[i] = 0; }
}

__global__ void k_deg(const int* __restrict__ row) {
    int e = blockIdx.x * blockDim.x + threadIdx.x;
    if (e < EE) {
        int r = row[e];
        if (r >= 0 && r < NN) atomicAdd(&g_degi[r], 1);
    }
}

__global__ __launch_bounds__(1024) void k_scan1() {
    __shared__ int s[1024];
    int i = blockIdx.x * 1024 + threadIdx.x;
    int v = (i < NN) ? g_degi[i] : 0;
    s[threadIdx.x] = v;
    __syncthreads();
    for (int off = 1; off < 1024; off <<= 1) {
        int a = (threadIdx.x >= off) ? s[threadIdx.x - off] : 0;
        __syncthreads();
        s[threadIdx.x] += a;
        __syncthreads();
    }
    if (i < NN) g_ptr[i] = s[threadIdx.x] - v;
    if (threadIdx.x == 1023) g_bsum[blockIdx.x] = s[1023];
}

__global__ __launch_bounds__(1024) void k_scan3() {
    __shared__ int s[128];
    const int b = blockIdx.x;
    const int t = threadIdx.x;
    if (t < 128) s[t] = (t < b) ? g_bsum[t] : 0;    // b <= NB-1 < 128
    __syncthreads();
    for (int o = 64; o > 0; o >>= 1) {
        if (t < o) s[t] += s[t + o];
        __syncthreads();
    }
    const int off = s[0];
    int i = b * 1024 + t;
    if (i < NN) {
        g_ptr[i] += off;
        int d = g_degi[i];
        g_dis[i] = (d > 0) ? rsqrtf((float)d) : 0.f;
    }
}

__global__ void k_fill(const int* __restrict__ row, const int* __restrict__ col) {
    int e = blockIdx.x * blockDim.x + threadIdx.x;
    if (e < EE) {
        int r = row[e];
        int c = col[e];
        if (r < 0 || r >= NN || c < 0 || c >= NN) return;
        int slot = g_ptr[r] + atomicAdd(&g_cnt[r], 1);
        float w = g_dis[r] * g_dis[c];
        g_csr_cw[slot] = make_int2(c, __float_as_int(w));
    }
}

// ---------------- tensor-core GEMM, layer 1: x[N,64] -> {H16, B16, C216} -----
// 128 nodes/block, 24 warps: q = wid>>3 selects output, slab = wid&7 the 16-row
// M tile. W staged once per 128 rows (half the traffic of the 64-row version).
__global__ __launch_bounds__(768) void k_gemm1(const float* __restrict__ x,
                                               const float* __restrict__ b1) {
    __shared__ alignas(16) __half sA[128][72];     // [m=node][k=ch]
    __shared__ alignas(16) __half sW[3][64][72];   // [which][n][k]
    const int nbase = blockIdx.x * 128;
    const int tid   = threadIdx.x;

    // x (fp32) -> fp16 A tile
    for (int i = tid; i < 2048; i += 768) {
        int n = i >> 4, c4 = i & 15;
        float4 v = make_float4(0.f, 0.f, 0.f, 0.f);
        if (nbase + n < NN)
            v = reinterpret_cast<const float4*>(x)[(size_t)(nbase + n) * 16 + c4];
        *reinterpret_cast<uint2*>(&sA[n][c4 * 4]) =
            make_uint2(f2h(v.x, v.y), f2h(v.z, v.w));
    }
    // W: straight uint4 copy of the pre-transposed image (conflict-free)
    {
        const uint4* wsrc = reinterpret_cast<const uint4*>(g_W1t);
        uint4* wdst = reinterpret_cast<uint4*>(&sW[0][0][0]);
        for (int i = tid; i < 3 * 64 * 72 / 8; i += 768) wdst[i] = wsrc[i];
    }
    __syncthreads();

    const int wid  = tid >> 5, lane = tid & 31;
    const int q    = wid >> 3, slab = wid & 7;
    const int m0   = slab * 16;

    float c[8][4];
#pragma unroll
    for (int j = 0; j < 8; j++)
#pragma unroll
        for (int p = 0; p < 4; p++) c[j][p] = 0.f;

    const int brow = lane & 7;
    const int bksub = ((lane >> 3) & 1) * 8;
    const int bjsub = (lane >> 4) & 1;

#pragma unroll
    for (int kc = 0; kc < 4; kc++) {
        const int k0 = kc * 16;
        int arow = m0 + (lane & 7) + ((lane >> 3) & 1) * 8;
        int acol = k0 + (lane >> 4) * 8;
        unsigned a0, a1, a2, a3;
        ldsm_x4(a0, a1, a2, a3, sptr(&sA[arow][acol]));
        unsigned b[8][2];
#pragma unroll
        for (int j = 0; j < 8; j += 2)
            ldsm_x4(b[j][0], b[j][1], b[j + 1][0], b[j + 1][1],
                    sptr(&sW[q][(j + bjsub) * 8 + brow][k0 + bksub]));
#pragma unroll
        for (int j = 0; j < 8; j++)
            mma_16816(c[j], a0, a1, a2, a3, b[j][0], b[j][1]);
    }

    const int r = lane >> 2, cp = (lane & 3) * 2;
    __half* dst = (q == 0) ? g_H16 : (q == 1) ? g_B16 : g_C216;
#pragma unroll
    for (int j = 0; j < 8; j++) {
        int colj = j * 8 + cp;
        float bv0 = 0.f, bv1 = 0.f;
        if (q == 0) { bv0 = __ldg(&b1[colj]); bv1 = __ldg(&b1[colj + 1]); }
        int m = nbase + m0 + r;
        if (m < NN)
            *reinterpret_cast<unsigned*>(dst + (size_t)m * 64 + colj) =
                f2h(c[j][0] + bv0, c[j][1] + bv1);
        if (m + 8 < NN)
            *reinterpret_cast<unsigned*>(dst + (size_t)(m + 8) * 64 + colj) =
                f2h(c[j][2] + bv0, c[j][3] + bv1);
    }
}

// ---------------- tensor-core GEMM, layer 2: relu(H16) -> {out, B216, C2216} -
__global__ __launch_bounds__(768) void k_gemm2(float* __restrict__ out,
                                               const float* __restrict__ b2) {
    __shared__ alignas(16) __half sA[128][72];
    __shared__ alignas(16) __half sW[3][32][72];
    const int nbase = blockIdx.x * 128;
    const int tid   = threadIdx.x;

    for (int i = tid; i < 1024; i += 768) {
        int n = i >> 3, c8 = i & 7;
        uint4 v = make_uint4(0u, 0u, 0u, 0u);
        if (nbase + n < NN) {
            v = *reinterpret_cast<const uint4*>(g_H16 + (size_t)(nbase + n) * 64 + c8 * 8);
            v.x = hrelu(v.x); v.y = hrelu(v.y); v.z = hrelu(v.z); v.w = hrelu(v.w);
        }
        *reinterpret_cast<uint4*>(&sA[n][c8 * 8]) = v;
    }
    {
        const uint4* wsrc = reinterpret_cast<const uint4*>(g_W2t);
        uint4* wdst = reinterpret_cast<uint4*>(&sW[0][0][0]);
        for (int i = tid; i < 3 * 32 * 72 / 8; i += 768) wdst[i] = wsrc[i];
    }
    __syncthreads();

    const int wid  = tid >> 5, lane = tid & 31;
    const int q    = wid >> 3, slab = wid & 7;
    const int m0   = slab * 16;

    float c[4][4];
#pragma unroll
    for (int j = 0; j < 4; j++)
#pragma unroll
        for (int p = 0; p < 4; p++) c[j][p] = 0.f;

    const int brow = lane & 7;
    const int bksub = ((lane >> 3) & 1) * 8;
    const int bjsub = (lane >> 4) & 1;

#pragma unroll
    for (int kc = 0; kc < 4; kc++) {
        const int k0 = kc * 16;
        int arow = m0 + (lane & 7) + ((lane >> 3) & 1) * 8;
        int acol = k0 + (lane >> 4) * 8;
        unsigned a0, a1, a2, a3;
        ldsm_x4(a0, a1, a2, a3, sptr(&sA[arow][acol]));
        unsigned b[4][2];
#pragma unroll
        for (int j = 0; j < 4; j += 2)
            ldsm_x4(b[j][0], b[j][1], b[j + 1][0], b[j + 1][1],
                    sptr(&sW[q][(j + bjsub) * 8 + brow][k0 + bksub]));
#pragma unroll
        for (int j = 0; j < 4; j++)
            mma_16816(c[j], a0, a1, a2, a3, b[j][0], b[j][1]);
    }

    const int r = lane >> 2, cp = (lane & 3) * 2;
#pragma unroll
    for (int j = 0; j < 4; j++) {
        int colj = j * 8 + cp;
        int m = nbase + m0 + r;
        if (q == 0) {
            float bv0 = __ldg(&b2[colj]), bv1 = __ldg(&b2[colj + 1]);
            if (m < NN)
                *reinterpret_cast<float2*>(out + (size_t)m * 32 + colj) =
                    make_float2(c[j][0] + bv0, c[j][1] + bv1);
            if (m + 8 < NN)
                *reinterpret_cast<float2*>(out + (size_t)(m + 8) * 32 + colj) =
                    make_float2(c[j][2] + bv0, c[j][3] + bv1);
        } else {
            __half* dst = (q == 1) ? g_B216 : g_C2216;
            if (m < NN)
                *reinterpret_cast<unsigned*>(dst + (size_t)m * 32 + colj) =
                    f2h(c[j][0], c[j][1]);
            if (m + 8 < NN)
                *reinterpret_cast<unsigned*>(dst + (size_t)(m + 8) * 32 + colj) =
                    f2h(c[j][2], c[j][3]);
        }
    }
}

// ---------------- fp16 pull propagation (16B/thread) --------------------------
template <int G, int MODE>
__global__ __launch_bounds__(256) void k_prop16(float* __restrict__ dout, float scale) {
    constexpr int C = G * 8;
    unsigned t = blockIdx.x * 256u + threadIdx.x;
    unsigned r = t / G;
    unsigned g = t & (G - 1);
    if (r >= NN) return;

    const __half* src;
    __half* dsth = nullptr;
    if (MODE == 0)      { src = g_C216;  dsth = g_B16;  }
    else if (MODE == 1) { src = g_B16;   dsth = g_H16;  }
    else if (MODE == 2) { src = g_C2216; dsth = g_B216; }
    else                { src = g_B216; }

    int e  = g_ptr[r];
    int e1 = (r == NN - 1) ? EE : g_ptr[r + 1];

    float a0[8], a1[8];
#pragma unroll
    for (int j = 0; j < 8; j++) { a0[j] = 0.f; a1[j] = 0.f; }

    for (; e + 1 < e1; e += 2) {
        int2 cw0 = __ldg(&g_csr_cw[e]);
        int2 cw1 = __ldg(&g_csr_cw[e + 1]);
        float w0 = __int_as_float(cw0.y);
        float w1 = __int_as_float(cw1.y);
        uint4 v0 = *reinterpret_cast<const uint4*>(src + (size_t)cw0.x * C + g * 8);
        uint4 v1 = *reinterpret_cast<const uint4*>(src + (size_t)cw1.x * C + g * 8);
        float2 f;
        f = h2f(v0.x); a0[0] += w0 * f.x; a0[1] += w0 * f.y;
        f = h2f(v0.y); a0[2] += w0 * f.x; a0[3] += w0 * f.y;
        f = h2f(v0.z); a0[4] += w0 * f.x; a0[5] += w0 * f.y;
        f = h2f(v0.w); a0[6] += w0 * f.x; a0[7] += w0 * f.y;
        f = h2f(v1.x); a1[0] += w1 * f.x; a1[1] += w1 * f.y;
        f = h2f(v1.y); a1[2] += w1 * f.x; a1[3] += w1 * f.y;
        f = h2f(v1.z); a1[4] += w1 * f.x; a1[5] += w1 * f.y;
        f = h2f(v1.w); a1[6] += w1 * f.x; a1[7] += w1 * f.y;
    }
    if (e < e1) {
        int2 cw0 = __ldg(&g_csr_cw[e]);
        float w0 = __int_as_float(cw0.y);
        uint4 v0 = *reinterpret_cast<const uint4*>(src + (size_t)cw0.x * C + g * 8);
        float2 f;
        f = h2f(v0.x); a0[0] += w0 * f.x; a0[1] += w0 * f.y;
        f = h2f(v0.y); a0[2] += w0 * f.x; a0[3] += w0 * f.y;
        f = h2f(v0.z); a0[4] += w0 * f.x; a0[5] += w0 * f.y;
        f = h2f(v0.w); a0[6] += w0 * f.x; a0[7] += w0 * f.y;
    }
#pragma unroll
    for (int j = 0; j < 8; j++) a0[j] = a0[j] + a1[j];

    if (MODE == 3) {
        float* p = dout + (size_t)r * 32 + g * 8;
        float4 d0 = *reinterpret_cast<float4*>(p);
        float4 d1 = *reinterpret_cast<float4*>(p + 4);
        d0.x += scale * a0[0]; d0.y += scale * a0[1];
        d0.z += scale * a0[2]; d0.w += scale * a0[3];
        d1.x += scale * a0[4]; d1.y += scale * a0[5];
        d1.z += scale * a0[6]; d1.w += scale * a0[7];
        *reinterpret_cast<float4*>(p)     = d0;
        *reinterpret_cast<float4*>(p + 4) = d1;
    } else {
        __half* p = dsth + (size_t)r * C + g * 8;
        uint4 dv = *reinterpret_cast<uint4*>(p);
        float2 f0 = h2f(dv.x), f1 = h2f(dv.y), f2 = h2f(dv.z), f3 = h2f(dv.w);
        dv.x = f2h(f0.x + scale * a0[0], f0.y + scale * a0[1]);
        dv.y = f2h(f1.x + scale * a0[2], f1.y + scale * a0[3]);
        dv.z = f2h(f2.x + scale * a0[4], f2.y + scale * a0[5]);
        dv.w = f2h(f3.x + scale * a0[6], f3.y + scale * a0[7]);
        *reinterpret_cast<uint4*>(p) = dv;
    }
}

// ---------------- launch ------------------------------------------------------
// Single stream; gemm1 kept as 4th launch (ncu's profiled slot).
extern "C" void kernel_launch(void* const* d_in, const int* in_sizes, int n_in,
                              void* d_out, int out_size) {
    const float* x   = (const float*)d_in[0];
    const int*   ei  = (const int*)d_in[1];     // int32 (JAX x64 disabled)
    const float* W1  = (const float*)d_in[2];
    const float* b1  = (const float*)d_in[3];
    const float* W2  = (const float*)d_in[4];
    const float* b2  = (const float*)d_in[5];
    float*       out = (float*)d_out;

    const int* row = ei;
    const int* col = ei + EE;

    const int TB = 256;

    k_wprep<<<12, 384>>>(W1, W2);                  // weight fold/transpose (parallel)
    k_init <<<(NN + TB - 1) / TB, TB>>>();
    k_deg  <<<(EE + TB - 1) / TB, TB>>>(row);
    k_gemm1<<<(NN + 127) / 128, 768>>>(x, b1);     // 4th launch -> profiled
    k_scan1<<<NB, 1024>>>();
    k_scan3<<<NB, 1024>>>();
    k_fill <<<(EE + TB - 1) / TB, TB>>>(row, col);

    // B += 2*P(C2)   (P = -A_norm -> scale = -2)
    k_prop16<8, 0><<<((unsigned)NN * 8 + TB - 1) / TB, TB>>>(out, -2.0f);
    // H += P(B)
    k_prop16<8, 1><<<((unsigned)NN * 8 + TB - 1) / TB, TB>>>(out, -1.0f);

    // Layer 2 (relu on load): out = relu(H)@(W0'-W2')+b2, B2, C22
    k_gemm2<<<(NN + 127) / 128, 768>>>(out, b2);
    // B2 += 2*P(C22)
    k_prop16<4, 2><<<((unsigned)NN * 4 + TB - 1) / TB, TB>>>(out, -2.0f);
    // out += P(B2)
    k_prop16<4, 3><<<((unsigned)NN * 4 + TB - 1) / TB, TB>>>(out, -1.0f);
}

// round 17
// speedup vs baseline: 1.3830x; 1.3830x over previous
#include <cuda_runtime.h>
#include <cuda_fp16.h>

#define NN 100000
#define EE 1200000
#define NB 98            // ceil(NN / 1024)
#define GEMM_BLOCKS 296  // 2 per SM x 148 SMs (persistent tile loop)

// ---------------- scratch (device globals; no allocation allowed) ------------
__device__ __align__(16) int    g_degi[NN];
__device__ __align__(16) int    g_cnt [NN];
__device__ __align__(16) int    g_ptr [NN];       // CSR row start (exclusive scan)
__device__ __align__(16) int    g_bsum[NB];
__device__ __align__(16) float  g_dis [NN];
__device__ __align__(16) int2   g_csr_cw[EE];     // packed {col, w-as-bits}
// fp16 intermediates
__device__ __align__(16) __half g_H16  [(size_t)NN * 64];
__device__ __align__(16) __half g_B16  [(size_t)NN * 64];
__device__ __align__(16) __half g_C216 [(size_t)NN * 64];
__device__ __align__(16) __half g_B216 [(size_t)NN * 32];
__device__ __align__(16) __half g_C2216[(size_t)NN * 32];
// pre-transposed fp16 weights in EXACT smem layout ([q][n][k], row stride 72)
__device__ __align__(16) __half g_W1t[3 * 64 * 72];
__device__ __align__(16) __half g_W2t[3 * 32 * 72];

// ---------------- helpers ------------------------------------------------------
__device__ __forceinline__ float2 h2f(unsigned u) {
    __half2 h = *reinterpret_cast<__half2*>(&u);
    return __half22float2(h);
}
__device__ __forceinline__ unsigned f2h(float a, float b) {
    __half2 h = __floats2half2_rn(a, b);
    return *reinterpret_cast<unsigned*>(&h);
}
__device__ __forceinline__ unsigned hrelu(unsigned u) {
    __half2 h = *reinterpret_cast<__half2*>(&u);
    h = __hmax2(h, __floats2half2_rn(0.f, 0.f));
    return *reinterpret_cast<unsigned*>(&h);
}
__device__ __forceinline__ unsigned sptr(const void* p) {
    return (unsigned)__cvta_generic_to_shared(p);
}
__device__ __forceinline__ void ldsm_x4(unsigned& r0, unsigned& r1, unsigned& r2,
                                        unsigned& r3, unsigned addr) {
    asm volatile("ldmatrix.sync.aligned.m8n8.x4.shared.b16 {%0,%1,%2,%3}, [%4];"
                 : "=r"(r0), "=r"(r1), "=r"(r2), "=r"(r3) : "r"(addr));
}
__device__ __forceinline__ void mma_16816(float* c, unsigned a0, unsigned a1,
                                          unsigned a2, unsigned a3,
                                          unsigned b0, unsigned b1) {
    asm volatile(
        "mma.sync.aligned.m16n8k16.row.col.f32.f16.f16.f32 "
        "{%0,%1,%2,%3}, {%4,%5,%6,%7}, {%8,%9}, {%0,%1,%2,%3};"
        : "+f"(c[0]), "+f"(c[1]), "+f"(c[2]), "+f"(c[3])
        : "r"(a0), "r"(a1), "r"(a2), "r"(a3), "r"(b0), "r"(b1));
}

// ---------------- one-time weight prep (fold, transpose, fp16) ----------------
__global__ __launch_bounds__(384) void k_wprep(const float* __restrict__ W1,
                                               const float* __restrict__ W2) {
    int tid = blockIdx.x * 384 + threadIdx.x;
    int stride = gridDim.x * 384;
    for (int i = tid; i < 3 * 64 * 64; i += stride) {
        int q = i >> 12, rem = i & 4095;
        int n = rem >> 6, k = rem & 63;
        float w = W1[q * 4096 + k * 64 + n];
        if (q == 0) w -= W1[2 * 4096 + k * 64 + n];
        g_W1t[q * 64 * 72 + n * 72 + k] = __float2half_rn(w);
    }
    for (int i = tid; i < 3 * 32 * 64; i += stride) {
        int q = i >> 11, rem = i & 2047;
        int n = rem >> 6, k = rem & 63;
        float w = W2[q * 2048 + k * 32 + n];
        if (q == 0) w -= W2[2 * 2048 + k * 32 + n];
        g_W2t[q * 32 * 72 + n * 72 + k] = __float2half_rn(w);
    }
}

// ---------------- degree / CSR build -----------------------------------------
__global__ void k_init() {
    int i = blockIdx.x * blockDim.x + threadIdx.x;
    if (i < NN) { g_degi[i] = 0; g_cnt[i] = 0; }
}

__global__ void k_deg(const int* __restrict__ row) {
    int e = blockIdx.x * blockDim.x + threadIdx.x;
    if (e < EE) {
        int r = row[e];
        if (r >= 0 && r < NN) atomicAdd(&g_degi[r], 1);
    }
}

__global__ __launch_bounds__(1024) void k_scan1() {
    __shared__ int s[1024];
    int i = blockIdx.x * 1024 + threadIdx.x;
    int v = (i < NN) ? g_degi[i] : 0;
    s[threadIdx.x] = v;
    __syncthreads();
    for (int off = 1; off < 1024; off <<= 1) {
        int a = (threadIdx.x >= off) ? s[threadIdx.x - off] : 0;
        __syncthreads();
        s[threadIdx.x] += a;
        __syncthreads();
    }
    if (i < NN) g_ptr[i] = s[threadIdx.x] - v;
    if (threadIdx.x == 1023) g_bsum[blockIdx.x] = s[1023];
}

__global__ __launch_bounds__(1024) void k_scan3() {
    __shared__ int s[128];
    const int b = blockIdx.x;
    const int t = threadIdx.x;
    if (t < 128) s[t] = (t < b) ? g_bsum[t] : 0;    // b <= NB-1 < 128
    __syncthreads();
    for (int o = 64; o > 0; o >>= 1) {
        if (t < o) s[t] += s[t + o];
        __syncthreads();
    }
    const int off = s[0];
    int i = b * 1024 + t;
    if (i < NN) {
        g_ptr[i] += off;
        int d = g_degi[i];
        g_dis[i] = (d > 0) ? rsqrtf((float)d) : 0.f;
    }
}

__global__ void k_fill(const int* __restrict__ row, const int* __restrict__ col) {
    int e = blockIdx.x * blockDim.x + threadIdx.x;
    if (e < EE) {
        int r = row[e];
        int c = col[e];
        if (r < 0 || r >= NN || c < 0 || c >= NN) return;
        int slot = g_ptr[r] + atomicAdd(&g_cnt[r], 1);
        float w = g_dis[r] * g_dis[c];
        g_csr_cw[slot] = make_int2(c, __float_as_int(w));
    }
}

// ---------------- tensor-core GEMM, layer 1 (persistent blocks) --------------
// W staged into smem ONCE per block; grid-stride loop over 64-row M tiles.
__global__ __launch_bounds__(384) void k_gemm1(const float* __restrict__ x,
                                               const float* __restrict__ b1) {
    __shared__ alignas(16) __half sA[64][72];      // [m=node][k=ch]
    __shared__ alignas(16) __half sW[3][64][72];   // [which][n][k]
    const int tid = threadIdx.x;

    // W: one-time per block, straight uint4 copy (conflict-free)
    {
        const uint4* wsrc = reinterpret_cast<const uint4*>(g_W1t);
        uint4* wdst = reinterpret_cast<uint4*>(&sW[0][0][0]);
        for (int i = tid; i < 3 * 64 * 72 / 8; i += 384) wdst[i] = wsrc[i];
    }

    const int wid  = tid >> 5, lane = tid & 31;
    const int q    = wid >> 2, slab = wid & 3;
    const int m0   = slab * 16;
    const int brow = lane & 7;
    const int bksub = ((lane >> 3) & 1) * 8;
    const int bjsub = (lane >> 4) & 1;
    const int r = lane >> 2, cp = (lane & 3) * 2;
    __half* dst = (q == 0) ? g_H16 : (q == 1) ? g_B16 : g_C216;

    const int ntiles = (NN + 63) / 64;
    for (int tile = blockIdx.x; tile < ntiles; tile += GEMM_BLOCKS) {
        const int nbase = tile * 64;
        // x (fp32) -> fp16 A tile
        for (int i = tid; i < 1024; i += 384) {
            int n = i >> 4, c4 = i & 15;
            float4 v = make_float4(0.f, 0.f, 0.f, 0.f);
            if (nbase + n < NN)
                v = reinterpret_cast<const float4*>(x)[(size_t)(nbase + n) * 16 + c4];
            *reinterpret_cast<uint2*>(&sA[n][c4 * 4]) =
                make_uint2(f2h(v.x, v.y), f2h(v.z, v.w));
        }
        __syncthreads();

        float c[8][4];
#pragma unroll
        for (int j = 0; j < 8; j++)
#pragma unroll
            for (int p = 0; p < 4; p++) c[j][p] = 0.f;

#pragma unroll
        for (int kc = 0; kc < 4; kc++) {
            const int k0 = kc * 16;
            int arow = m0 + (lane & 7) + ((lane >> 3) & 1) * 8;
            int acol = k0 + (lane >> 4) * 8;
            unsigned a0, a1, a2, a3;
            ldsm_x4(a0, a1, a2, a3, sptr(&sA[arow][acol]));
            unsigned b[8][2];
#pragma unroll
            for (int j = 0; j < 8; j += 2)
                ldsm_x4(b[j][0], b[j][1], b[j + 1][0], b[j + 1][1],
                        sptr(&sW[q][(j + bjsub) * 8 + brow][k0 + bksub]));
#pragma unroll
            for (int j = 0; j < 8; j++)
                mma_16816(c[j], a0, a1, a2, a3, b[j][0], b[j][1]);
        }
        __syncthreads();   // mainloop done before next tile overwrites sA

#pragma unroll
        for (int j = 0; j < 8; j++) {
            int colj = j * 8 + cp;
            float bv0 = 0.f, bv1 = 0.f;
            if (q == 0) { bv0 = __ldg(&b1[colj]); bv1 = __ldg(&b1[colj + 1]); }
            int m = nbase + m0 + r;
            if (m < NN)
                *reinterpret_cast<unsigned*>(dst + (size_t)m * 64 + colj) =
                    f2h(c[j][0] + bv0, c[j][1] + bv1);
            if (m + 8 < NN)
                *reinterpret_cast<unsigned*>(dst + (size_t)(m + 8) * 64 + colj) =
                    f2h(c[j][2] + bv0, c[j][3] + bv1);
        }
    }
}

// ---------------- tensor-core GEMM, layer 2 (persistent blocks) --------------
__global__ __launch_bounds__(384) void k_gemm2(float* __restrict__ out,
                                               const float* __restrict__ b2) {
    __shared__ alignas(16) __half sA[64][72];
    __shared__ alignas(16) __half sW[3][32][72];
    const int tid = threadIdx.x;

    {
        const uint4* wsrc = reinterpret_cast<const uint4*>(g_W2t);
        uint4* wdst = reinterpret_cast<uint4*>(&sW[0][0][0]);
        for (int i = tid; i < 3 * 32 * 72 / 8; i += 384) wdst[i] = wsrc[i];
    }

    const int wid  = tid >> 5, lane = tid & 31;
    const int q    = wid >> 2, slab = wid & 3;
    const int m0   = slab * 16;
    const int brow = lane & 7;
    const int bksub = ((lane >> 3) & 1) * 8;
    const int bjsub = (lane >> 4) & 1;
    const int r = lane >> 2, cp = (lane & 3) * 2;

    const int ntiles = (NN + 63) / 64;
    for (int tile = blockIdx.x; tile < ntiles; tile += GEMM_BLOCKS) {
        const int nbase = tile * 64;
        for (int i = tid; i < 512; i += 384) {
            int n = i >> 3, c8 = i & 7;
            uint4 v = make_uint4(0u, 0u, 0u, 0u);
            if (nbase + n < NN) {
                v = *reinterpret_cast<const uint4*>(g_H16 + (size_t)(nbase + n) * 64 + c8 * 8);
                v.x = hrelu(v.x); v.y = hrelu(v.y); v.z = hrelu(v.z); v.w = hrelu(v.w);
            }
            *reinterpret_cast<uint4*>(&sA[n][c8 * 8]) = v;
        }
        __syncthreads();

        float c[4][4];
#pragma unroll
        for (int j = 0; j < 4; j++)
#pragma unroll
            for (int p = 0; p < 4; p++) c[j][p] = 0.f;

#pragma unroll
        for (int kc = 0; kc < 4; kc++) {
            const int k0 = kc * 16;
            int arow = m0 + (lane & 7) + ((lane >> 3) & 1) * 8;
            int acol = k0 + (lane >> 4) * 8;
            unsigned a0, a1, a2, a3;
            ldsm_x4(a0, a1, a2, a3, sptr(&sA[arow][acol]));
            unsigned b[4][2];
#pragma unroll
            for (int j = 0; j < 4; j += 2)
                ldsm_x4(b[j][0], b[j][1], b[j + 1][0], b[j + 1][1],
                        sptr(&sW[q][(j + bjsub) * 8 + brow][k0 + bksub]));
#pragma unroll
            for (int j = 0; j < 4; j++)
                mma_16816(c[j], a0, a1, a2, a3, b[j][0], b[j][1]);
        }
        __syncthreads();

#pragma unroll
        for (int j = 0; j < 4; j++) {
            int colj = j * 8 + cp;
            int m = nbase + m0 + r;
            if (q == 0) {
                float bv0 = __ldg(&b2[colj]), bv1 = __ldg(&b2[colj + 1]);
                if (m < NN)
                    *reinterpret_cast<float2*>(out + (size_t)m * 32 + colj) =
                        make_float2(c[j][0] + bv0, c[j][1] + bv1);
                if (m + 8 < NN)
                    *reinterpret_cast<float2*>(out + (size_t)(m + 8) * 32 + colj) =
                        make_float2(c[j][2] + bv0, c[j][3] + bv1);
            } else {
                __half* dsth = (q == 1) ? g_B216 : g_C2216;
                if (m < NN)
                    *reinterpret_cast<unsigned*>(dsth + (size_t)m * 32 + colj) =
                        f2h(c[j][0], c[j][1]);
                if (m + 8 < NN)
                    *reinterpret_cast<unsigned*>(dsth + (size_t)(m + 8) * 32 + colj) =
                        f2h(c[j][2], c[j][3]);
            }
        }
    }
}

// ---------------- fp16 pull propagation (16B/thread) --------------------------
template <int G, int MODE>
__global__ __launch_bounds__(256) void k_prop16(float* __restrict__ dout, float scale) {
    constexpr int C = G * 8;
    unsigned t = blockIdx.x * 256u + threadIdx.x;
    unsigned r = t / G;
    unsigned g = t & (G - 1);
    if (r >= NN) return;

    const __half* src;
    __half* dsth = nullptr;
    if (MODE == 0)      { src = g_C216;  dsth = g_B16;  }
    else if (MODE == 1) { src = g_B16;   dsth = g_H16;  }
    else if (MODE == 2) { src = g_C2216; dsth = g_B216; }
    else                { src = g_B216; }

    int e  = g_ptr[r];
    int e1 = (r == NN - 1) ? EE : g_ptr[r + 1];

    float a0[8], a1[8];
#pragma unroll
    for (int j = 0; j < 8; j++) { a0[j] = 0.f; a1[j] = 0.f; }

    for (; e + 1 < e1; e += 2) {
        int2 cw0 = __ldg(&g_csr_cw[e]);
        int2 cw1 = __ldg(&g_csr_cw[e + 1]);
        float w0 = __int_as_float(cw0.y);
        float w1 = __int_as_float(cw1.y);
        uint4 v0 = *reinterpret_cast<const uint4*>(src + (size_t)cw0.x * C + g * 8);
        uint4 v1 = *reinterpret_cast<const uint4*>(src + (size_t)cw1.x * C + g * 8);
        float2 f;
        f = h2f(v0.x); a0[0] += w0 * f.x; a0[1] += w0 * f.y;
        f = h2f(v0.y); a0[2] += w0 * f.x; a0[3] += w0 * f.y;
        f = h2f(v0.z); a0[4] += w0 * f.x; a0[5] += w0 * f.y;
        f = h2f(v0.w); a0[6] += w0 * f.x; a0[7] += w0 * f.y;
        f = h2f(v1.x); a1[0] += w1 * f.x; a1[1] += w1 * f.y;
        f = h2f(v1.y); a1[2] += w1 * f.x; a1[3] += w1 * f.y;
        f = h2f(v1.z); a1[4] += w1 * f.x; a1[5] += w1 * f.y;
        f = h2f(v1.w); a1[6] += w1 * f.x; a1[7] += w1 * f.y;
    }
    if (e < e1) {
        int2 cw0 = __ldg(&g_csr_cw[e]);
        float w0 = __int_as_float(cw0.y);
        uint4 v0 = *reinterpret_cast<const uint4*>(src + (size_t)cw0.x * C + g * 8);
        float2 f;
        f = h2f(v0.x); a0[0] += w0 * f.x; a0[1] += w0 * f.y;
        f = h2f(v0.y); a0[2] += w0 * f.x; a0[3] += w0 * f.y;
        f = h2f(v0.z); a0[4] += w0 * f.x; a0[5] += w0 * f.y;
        f = h2f(v0.w); a0[6] += w0 * f.x; a0[7] += w0 * f.y;
    }
#pragma unroll
    for (int j = 0; j < 8; j++) a0[j] = a0[j] + a1[j];

    if (MODE == 3) {
        float* p = dout + (size_t)r * 32 + g * 8;
        float4 d0 = *reinterpret_cast<float4*>(p);
        float4 d1 = *reinterpret_cast<float4*>(p + 4);
        d0.x += scale * a0[0]; d0.y += scale * a0[1];
        d0.z += scale * a0[2]; d0.w += scale * a0[3];
        d1.x += scale * a0[4]; d1.y += scale * a0[5];
        d1.z += scale * a0[6]; d1.w += scale * a0[7];
        *reinterpret_cast<float4*>(p)     = d0;
        *reinterpret_cast<float4*>(p + 4) = d1;
    } else {
        __half* p = dsth + (size_t)r * C + g * 8;
        uint4 dv = *reinterpret_cast<uint4*>(p);
        float2 f0 = h2f(dv.x), f1 = h2f(dv.y), f2 = h2f(dv.z), f3 = h2f(dv.w);
        dv.x = f2h(f0.x + scale * a0[0], f0.y + scale * a0[1]);
        dv.y = f2h(f1.x + scale * a0[2], f1.y + scale * a0[3]);
        dv.z = f2h(f2.x + scale * a0[4], f2.y + scale * a0[5]);
        dv.w = f2h(f3.x + scale * a0[6], f3.y + scale * a0[7]);
        *reinterpret_cast<uint4*>(p) = dv;
    }
}

// ---------------- launch ------------------------------------------------------
// Single stream; gemm1 kept as 4th launch (ncu's profiled slot).
extern "C" void kernel_launch(void* const* d_in, const int* in_sizes, int n_in,
                              void* d_out, int out_size) {
    const float* x   = (const float*)d_in[0];
    const int*   ei  = (const int*)d_in[1];     // int32 (JAX x64 disabled)
    const float* W1  = (const float*)d_in[2];
    const float* b1  = (const float*)d_in[3];
    const float* W2  = (const float*)d_in[4];
    const float* b2  = (const float*)d_in[5];
    float*       out = (float*)d_out;

    const int* row = ei;
    const int* col = ei + EE;

    const int TB = 256;

    k_wprep<<<12, 384>>>(W1, W2);                  // weight fold/transpose (parallel)
    k_init <<<(NN + TB - 1) / TB, TB>>>();
    k_deg  <<<(EE + TB - 1) / TB, TB>>>(row);
    k_gemm1<<<GEMM_BLOCKS, 384>>>(x, b1);          // 4th launch -> profiled
    k_scan1<<<NB, 1024>>>();
    k_scan3<<<NB, 1024>>>();
    k_fill <<<(EE + TB - 1) / TB, TB>>>(row, col);

    // B += 2*P(C2)   (P = -A_norm -> scale = -2)
    k_prop16<8, 0><<<((unsigned)NN * 8 + TB - 1) / TB, TB>>>(out, -2.0f);
    // H += P(B)
    k_prop16<8, 1><<<((unsigned)NN * 8 + TB - 1) / TB, TB>>>(out, -1.0f);

    // Layer 2 (relu on load): out = relu(H)@(W0'-W2')+b2, B2, C22
    k_gemm2<<<GEMM_BLOCKS, 384>>>(out, b2);
    // B2 += 2*P(C22)
    k_prop16<4, 2><<<((unsigned)NN * 4 + TB - 1) / TB, TB>>>(out, -2.0f);
    // out += P(B2)
    k_prop16<4, 3><<<((unsigned)NN * 4 + TB - 1) / TB, TB>>>(out, -1.0f);
}